// round 4
// baseline (speedup 1.0000x reference)
#include <cuda_runtime.h>
#include <cstdint>

#define BB    2
#define CC    64
#define NPOS  131072
#define HEADS 4
#define DHEAD 32
#define HID   128
#define TPB   256

typedef unsigned long long u64;

// ---------------- device scratch (static, allowed) ----------------
__device__ float g_q[(size_t)BB * HID * NPOS];         // softmaxed+scaled q, [b][h*32+d][n]
__device__ float g_ctx[BB * HEADS * DHEAD * DHEAD];    // raw sum exp(k_d)*v_e
__device__ float g_Z[BB * HEADS * DHEAD];              // sum exp(k_d)
__device__ float g_M[BB * HID * CC];                   // TRANSPOSED fold: Mt[b][i][o]

// ---------------- f32x2 helpers ----------------
__device__ __forceinline__ u64 pack2(float lo, float hi) {
    u64 r; asm("mov.b64 %0, {%1,%2};" : "=l"(r) : "f"(lo), "f"(hi)); return r;
}
__device__ __forceinline__ u64 ffma2(u64 a, u64 b, u64 c) {
    u64 d; asm("fma.rn.f32x2 %0, %1, %2, %3;" : "=l"(d) : "l"(a), "l"(b), "l"(c)); return d;
}
__device__ __forceinline__ u64 fadd2(u64 a, u64 b) {
    u64 d; asm("add.rn.f32x2 %0, %1, %2;" : "=l"(d) : "l"(a), "l"(b)); return d;
}
__device__ __forceinline__ float hsum2(u64 a) {
    float lo, hi; asm("mov.b64 {%0,%1}, %2;" : "=f"(lo), "=f"(hi) : "l"(a)); return lo + hi;
}
__device__ __forceinline__ void unpack2(u64 a, float& lo, float& hi) {
    asm("mov.b64 {%0,%1}, %2;" : "=f"(lo), "=f"(hi) : "l"(a));
}
// volatile global load (defeats CSE with the later re-load of the same address)
__device__ __forceinline__ float ldg_once(const float* p) {
    float v; asm volatile("ld.global.nc.f32 %0, [%1];" : "=f"(v) : "l"(p)); return v;
}

// 64-length dot: W row (smem, packed as pairs) . xp (regs, packed pairs)
__device__ __forceinline__ float dot64(const float* __restrict__ wrow, const u64* __restrict__ xp) {
    const ulonglong2* wp = (const ulonglong2*)wrow;
    u64 a0 = 0, a1 = 0, a2 = 0, a3 = 0;
#pragma unroll
    for (int i = 0; i < 8; i++) {
        ulonglong2 w0 = wp[2 * i];
        ulonglong2 w1 = wp[2 * i + 1];
        a0 = ffma2(w0.x, xp[4 * i + 0], a0);
        a1 = ffma2(w0.y, xp[4 * i + 1], a1);
        a2 = ffma2(w1.x, xp[4 * i + 2], a2);
        a3 = ffma2(w1.y, xp[4 * i + 3], a3);
    }
    return hsum2(fadd2(fadd2(a0, a1), fadd2(a2, a3)));
}

// ---------------- kernel 0: zero accumulators ----------------
__global__ void la_zero_kernel() {
    int i = blockIdx.x * blockDim.x + threadIdx.x;
    if (i < BB * HEADS * DHEAD * DHEAD) g_ctx[i] = 0.f;
    if (i < BB * HEADS * DHEAD)         g_Z[i]   = 0.f;
}

// ---------------- kernel 1: LN1 + qkv matvec + q softmax + ctx/Z partials ----------------
// smem: Wc[2048] g1s[64] b1s[64] ek[32*260] vv[32*260]  = 18816 floats = 75264 B
#define SM1_FLOATS (2048 + 64 + 64 + 32 * 260 + 32 * 260)

__device__ __forceinline__ void loadW(float* Wc, const float* __restrict__ src, int t) {
    __syncthreads();                       // prior consumers of Wc / tiles done
#pragma unroll
    for (int i = 0; i < 2; i++)
        ((float4*)Wc)[t + i * 256] = ((const float4*)src)[t + i * 256];
    __syncthreads();                       // chunk ready
}

__global__ __launch_bounds__(TPB, 2)
void la_pass1_kernel(const float* __restrict__ x, const float* __restrict__ g1,
                     const float* __restrict__ b1, const float* __restrict__ wqkv) {
    extern __shared__ float sm1[];
    float* Wc  = sm1;                // 2048
    float* g1s = Wc + 2048;          // 64
    float* b1s = g1s + 64;           // 64
    float* ek  = b1s + 64;           // 32*260  (also q scratch)
    float* vv  = ek + 32 * 260;      // 32*260

    const int t   = threadIdx.x;
    const int bb  = blockIdx.y;
    const int pos = blockIdx.x * TPB + t;

    if (t < 64) { g1s[t] = g1[t]; b1s[t] = b1[t]; }

    // ---- pass A: LN stats only (volatile loads — no 64-wide live range) ----
    const float* xb = x + (size_t)bb * CC * NPOS + pos;
    float s = 0.f, s2 = 0.f;
#pragma unroll
    for (int c = 0; c < 64; c++) {
        float v = ldg_once(xb + (size_t)c * NPOS);
        s += v; s2 += v * v;
    }
    float mean = s * (1.f / 64.f);
    float rstd = rsqrtf(s2 * (1.f / 64.f) - mean * mean + 1e-5f);
    __syncthreads();                       // g1s/b1s ready

    // ---- pass B: reload (L1-hot) + normalize + pack ----
    u64 xp[32];
#pragma unroll
    for (int i = 0; i < 32; i++) {
        float a  = (__ldg(xb + (size_t)(2 * i)     * NPOS) - mean) * rstd * g1s[2 * i]     + b1s[2 * i];
        float bv = (__ldg(xb + (size_t)(2 * i + 1) * NPOS) - mean) * rstd * g1s[2 * i + 1] + b1s[2 * i + 1];
        xp[i] = pack2(a, bv);
    }

    const int d_own = t >> 3;       // 0..31
    const int e0    = t & 7;        // 0..7

    for (int h = 0; h < HEADS; h++) {
        // ---------- Q (max tracked during dot phase) ----------
        loadW(Wc, wqkv + (size_t)(h * 32) * 64, t);
        float mx = -1e30f;
        for (int d = 0; d < 32; d++) {
            float v = dot64(Wc + d * 64, xp);
            ek[d * 260 + t] = v;
            mx = fmaxf(mx, v);
        }
        float ss = 0.f;
        for (int d = 0; d < 32; d++) {
            float e = __expf(ek[d * 260 + t] - mx);
            ek[d * 260 + t] = e; ss += e;
        }
        float qsc = 0.17677669529663687f / ss;     // DIM_HEAD^-0.5 / sum
        float* qg = g_q + (size_t)(bb * HID + h * 32) * NPOS + pos;
        for (int d = 0; d < 32; d++)
            qg[(size_t)d * NPOS] = ek[d * 260 + t] * qsc;

        // ---------- K (exp, no max subtraction; values ~N(0,1)) ----------
        loadW(Wc, wqkv + (size_t)(HID + h * 32) * 64, t);
        for (int d = 0; d < 32; d++)
            ek[d * 260 + t] = __expf(dot64(Wc + d * 64, xp));

        // ---------- V ----------
        loadW(Wc, wqkv + (size_t)(2 * HID + h * 32) * 64, t);
        for (int d = 0; d < 32; d++)
            vv[d * 260 + t] = dot64(Wc + d * 64, xp);
        __syncthreads();

        // ---------- stage B: ctx[d,e] += sum_tt ek[d,tt]*vv[e,tt], Z[d] += sum ek ----------
        u64 acc0 = 0, acc1 = 0, acc2 = 0, acc3 = 0, za = 0;
        const float* ekr = ek + d_own * 260;
#pragma unroll 4
        for (int tt = 0; tt < TPB; tt += 4) {
            ulonglong2 ap  = *(const ulonglong2*)(ekr + tt);
            ulonglong2 bv0 = *(const ulonglong2*)(vv + (e0     ) * 260 + tt);
            ulonglong2 bv1 = *(const ulonglong2*)(vv + (e0 +  8) * 260 + tt);
            ulonglong2 bv2 = *(const ulonglong2*)(vv + (e0 + 16) * 260 + tt);
            ulonglong2 bv3 = *(const ulonglong2*)(vv + (e0 + 24) * 260 + tt);
            acc0 = ffma2(ap.x, bv0.x, acc0); acc0 = ffma2(ap.y, bv0.y, acc0);
            acc1 = ffma2(ap.x, bv1.x, acc1); acc1 = ffma2(ap.y, bv1.y, acc1);
            acc2 = ffma2(ap.x, bv2.x, acc2); acc2 = ffma2(ap.y, bv2.y, acc2);
            acc3 = ffma2(ap.x, bv3.x, acc3); acc3 = ffma2(ap.y, bv3.y, acc3);
            if (e0 == 0) za = fadd2(za, fadd2(ap.x, ap.y));
        }
        float* cb = g_ctx + (size_t)((bb * HEADS + h) * DHEAD + d_own) * DHEAD;
        atomicAdd(cb + e0,      hsum2(acc0));
        atomicAdd(cb + e0 +  8, hsum2(acc1));
        atomicAdd(cb + e0 + 16, hsum2(acc2));
        atomicAdd(cb + e0 + 24, hsum2(acc3));
        if (e0 == 0) atomicAdd(g_Z + (bb * HEADS + h) * DHEAD + d_own, hsum2(za));
        // next head's loadW pre-sync protects tile reuse
    }
}

// ---------------- kernel 2: fold  Mt[i=h*32+d][o] = sum_e W_out[o][h*32+e] * ctx[h,d,e] / Z[h,d]
__global__ void la_fold_kernel(const float* __restrict__ wout) {
    int bb = blockIdx.x;
    for (int idx = threadIdx.x; idx < HID * CC; idx += blockDim.x) {
        int i  = idx >> 6;        // hid index (h*32+d)
        int o  = idx & 63;        // output channel
        int h  = i >> 5;
        int d  = i & 31;
        const float* cp = g_ctx + (size_t)((bb * HEADS + h) * DHEAD + d) * DHEAD;
        const float* wp = wout + (size_t)o * HID + h * DHEAD;
        float acc = 0.f;
#pragma unroll
        for (int e = 0; e < 32; e++) acc += wp[e] * cp[e];
        g_M[(size_t)bb * HID * CC + idx] = acc / g_Z[(bb * HEADS + h) * DHEAD + d];
    }
}

// ---------------- kernel 3: y = LN2( Mt^T @ q + b_out ), register accumulators ----------------
// smem: Mt[8192] bo[64] g2s[64] b2s[64] = 8384 floats = 33536 B
#define SM2_FLOATS (8192 + 64 + 64 + 64)

__global__ __launch_bounds__(TPB, 2)
void la_pass2_kernel(const float* __restrict__ bout, const float* __restrict__ g2,
                     const float* __restrict__ b2, float* __restrict__ out) {
    extern __shared__ float sm2[];
    float* Mt  = sm2;             // 8192  (layout [i][o], o contiguous)
    float* bo  = Mt + 8192;       // 64
    float* g2s = bo + 64;         // 64
    float* b2s = g2s + 64;        // 64

    const int t   = threadIdx.x;
    const int bb  = blockIdx.y;
    const int pos = blockIdx.x * TPB + t;

    for (int i = t; i < (HID * CC) / 4; i += TPB)
        ((float4*)Mt)[i] = ((const float4*)(g_M + (size_t)bb * HID * CC))[i];
    if (t < 64) { bo[t] = bout[t]; g2s[t] = g2[t]; b2s[t] = b2[t]; }
    __syncthreads();

    const float* qb = g_q + (size_t)bb * HID * NPOS + pos;

    // 32 packed accumulators: acc[k] = (y[2k], y[2k+1])
    u64 acc[32];
#pragma unroll
    for (int k = 0; k < 32; k++) acc[k] = 0;

    // software-prefetched q, chunks of 8
    float qbuf[8];
#pragma unroll
    for (int j = 0; j < 8; j++) qbuf[j] = __ldg(qb + (size_t)j * NPOS);

    for (int i0 = 0; i0 < HID; i0 += 8) {
        float qn[8];
#pragma unroll
        for (int j = 0; j < 8; j++) {
            int nx = i0 + 8 + j;
            qn[j] = __ldg(qb + (size_t)(nx < HID ? nx : HID - 1) * NPOS);
        }
#pragma unroll
        for (int j = 0; j < 8; j++) {
            u64 qv = pack2(qbuf[j], qbuf[j]);
            const ulonglong2* mp = (const ulonglong2*)(Mt + (i0 + j) * 64);
#pragma unroll
            for (int k = 0; k < 16; k++) {
                ulonglong2 m = mp[k];
                acc[2 * k]     = ffma2(m.x, qv, acc[2 * k]);
                acc[2 * k + 1] = ffma2(m.y, qv, acc[2 * k + 1]);
            }
        }
#pragma unroll
        for (int j = 0; j < 8; j++) qbuf[j] = qn[j];
    }

    // unpack + bias + LN over 64 channels, all in registers
    float y[64];
    float s = 0.f, s2 = 0.f;
#pragma unroll
    for (int k = 0; k < 32; k++) {
        float lo, hi; unpack2(acc[k], lo, hi);
        lo += bo[2 * k]; hi += bo[2 * k + 1];
        y[2 * k] = lo; y[2 * k + 1] = hi;
        s += lo + hi; s2 += lo * lo + hi * hi;
    }
    float mean = s * (1.f / 64.f);
    float rstd = rsqrtf(s2 * (1.f / 64.f) - mean * mean + 1e-5f);
    float* ob = out + (size_t)bb * CC * NPOS + pos;
#pragma unroll
    for (int o = 0; o < 64; o++)
        ob[(size_t)o * NPOS] = (y[o] - mean) * rstd * g2s[o] + b2s[o];
}

// ---------------- launch ----------------
extern "C" void kernel_launch(void* const* d_in, const int* in_sizes, int n_in,
                              void* d_out, int out_size) {
    (void)in_sizes; (void)n_in; (void)out_size;
    const float* x    = (const float*)d_in[0];
    const float* g1   = (const float*)d_in[1];
    const float* b1   = (const float*)d_in[2];
    const float* wqkv = (const float*)d_in[3];
    const float* wout = (const float*)d_in[4];
    const float* bout = (const float*)d_in[5];
    const float* g2   = (const float*)d_in[6];
    const float* b2   = (const float*)d_in[7];
    float* y = (float*)d_out;

    cudaFuncSetAttribute(la_pass1_kernel, cudaFuncAttributeMaxDynamicSharedMemorySize,
                         SM1_FLOATS * (int)sizeof(float));
    cudaFuncSetAttribute(la_pass2_kernel, cudaFuncAttributeMaxDynamicSharedMemorySize,
                         SM2_FLOATS * (int)sizeof(float));

    la_zero_kernel<<<33, 256>>>();
    la_pass1_kernel<<<dim3(NPOS / TPB, BB), TPB, SM1_FLOATS * sizeof(float)>>>(x, g1, b1, wqkv);
    la_fold_kernel<<<BB, 256>>>(wout);
    la_pass2_kernel<<<dim3(NPOS / TPB, BB), TPB, SM2_FLOATS * sizeof(float)>>>(bout, g2, b2, y);
}

// round 7
// speedup vs baseline: 1.6023x; 1.6023x over previous
#include <cuda_runtime.h>
#include <cstdint>

#define BB    2
#define CC    64
#define NPOS  131072
#define HEADS 4
#define DHEAD 32
#define HID   128
#define TPB   256

typedef unsigned long long u64;

// ---------------- device scratch (static, allowed) ----------------
__device__ float g_q[(size_t)BB * HID * NPOS];         // softmaxed+scaled q, [b][h*32+d][n]
__device__ float g_ctx[BB * HEADS * DHEAD * DHEAD];    // raw sum exp(k_d)*v_e
__device__ float g_Z[BB * HEADS * DHEAD];              // sum exp(k_d)
__device__ float g_M[BB * HID * CC];                   // TRANSPOSED fold: Mt[b][i][o]

// ---------------- f32x2 helpers ----------------
__device__ __forceinline__ u64 pack2(float lo, float hi) {
    u64 r; asm("mov.b64 %0, {%1,%2};" : "=l"(r) : "f"(lo), "f"(hi)); return r;
}
__device__ __forceinline__ u64 ffma2(u64 a, u64 b, u64 c) {
    u64 d; asm("fma.rn.f32x2 %0, %1, %2, %3;" : "=l"(d) : "l"(a), "l"(b), "l"(c)); return d;
}
__device__ __forceinline__ u64 fadd2(u64 a, u64 b) {
    u64 d; asm("add.rn.f32x2 %0, %1, %2;" : "=l"(d) : "l"(a), "l"(b)); return d;
}
__device__ __forceinline__ float hsum2(u64 a) {
    float lo, hi; asm("mov.b64 {%0,%1}, %2;" : "=f"(lo), "=f"(hi) : "l"(a)); return lo + hi;
}
__device__ __forceinline__ void unpack2(u64 a, float& lo, float& hi) {
    asm("mov.b64 {%0,%1}, %2;" : "=f"(lo), "=f"(hi) : "l"(a));
}

// 64-length dot: W row (smem, packed as pairs) . xp (regs, packed pairs)
__device__ __forceinline__ float dot64(const float* __restrict__ wrow, const u64* __restrict__ xp) {
    const ulonglong2* wp = (const ulonglong2*)wrow;
    u64 a0 = 0, a1 = 0, a2 = 0, a3 = 0;
#pragma unroll
    for (int i = 0; i < 8; i++) {
        ulonglong2 w0 = wp[2 * i];
        ulonglong2 w1 = wp[2 * i + 1];
        a0 = ffma2(w0.x, xp[4 * i + 0], a0);
        a1 = ffma2(w0.y, xp[4 * i + 1], a1);
        a2 = ffma2(w1.x, xp[4 * i + 2], a2);
        a3 = ffma2(w1.y, xp[4 * i + 3], a3);
    }
    return hsum2(fadd2(fadd2(a0, a1), fadd2(a2, a3)));
}

// ---------------- kernel 0: zero accumulators ----------------
__global__ void la_zero_kernel() {
    int i = blockIdx.x * blockDim.x + threadIdx.x;
    if (i < BB * HEADS * DHEAD * DHEAD) g_ctx[i] = 0.f;
    if (i < BB * HEADS * DHEAD)         g_Z[i]   = 0.f;
}

// ---------------- kernel 1: LN1 + qkv matvec + q softmax + ctx/Z partials ----------------
// smem: Wc[2048] g1s[64] b1s[64] ek[32*260] vv[32*260]  = 18816 floats = 75264 B
#define SM1_FLOATS (2048 + 64 + 64 + 32 * 260 + 32 * 260)

__device__ __forceinline__ void loadW(float* Wc, const float* __restrict__ src, int t) {
    __syncthreads();                       // prior consumers of Wc / tiles done
#pragma unroll
    for (int i = 0; i < 2; i++)
        ((float4*)Wc)[t + i * 256] = ((const float4*)src)[t + i * 256];
    __syncthreads();                       // chunk ready
}

__global__ __launch_bounds__(TPB, 2)
void la_pass1_kernel(const float* __restrict__ x, const float* __restrict__ g1,
                     const float* __restrict__ b1, const float* __restrict__ wqkv) {
    extern __shared__ float sm1[];
    float* Wc  = sm1;                // 2048
    float* g1s = Wc + 2048;          // 64
    float* b1s = g1s + 64;           // 64
    float* ek  = b1s + 64;           // 32*260  (also q scratch)
    float* vv  = ek + 32 * 260;      // 32*260

    const int t   = threadIdx.x;
    const int bb  = blockIdx.y;
    const int pos = blockIdx.x * TPB + t;

    if (t < 64) { g1s[t] = g1[t]; b1s[t] = b1[t]; }

    // ---- load x straight into packed pairs; LN stats on packed accumulators ----
    const float* xb = x + (size_t)bb * CC * NPOS + pos;
    u64 xp[32];
    u64 sa = 0, s2a = 0;
#pragma unroll
    for (int i = 0; i < 32; i++) {
        float a  = __ldg(xb + (size_t)(2 * i)     * NPOS);
        float bv = __ldg(xb + (size_t)(2 * i + 1) * NPOS);
        u64 p = pack2(a, bv);
        xp[i] = p;
        sa  = fadd2(sa, p);
        s2a = ffma2(p, p, s2a);
    }
    float s  = hsum2(sa);
    float s2 = hsum2(s2a);
    float mean = s * (1.f / 64.f);
    float rstd = rsqrtf(s2 * (1.f / 64.f) - mean * mean + 1e-5f);
    __syncthreads();                       // g1s/b1s ready

    // normalize in place: x' = x*k1 + k2,  k1 = rstd*g,  k2 = b - mean*k1
#pragma unroll
    for (int i = 0; i < 32; i++) {
        float k1a = rstd * g1s[2 * i];
        float k1b = rstd * g1s[2 * i + 1];
        float k2a = b1s[2 * i]     - mean * k1a;
        float k2b = b1s[2 * i + 1] - mean * k1b;
        xp[i] = ffma2(xp[i], pack2(k1a, k1b), pack2(k2a, k2b));
    }

    const int d_own = t >> 3;       // 0..31
    const int e0    = t & 7;        // 0..7

    for (int h = 0; h < HEADS; h++) {
        // ---------- Q (max tracked during dot phase) ----------
        loadW(Wc, wqkv + (size_t)(h * 32) * 64, t);
        float mx = -1e30f;
        for (int d = 0; d < 32; d++) {
            float v = dot64(Wc + d * 64, xp);
            ek[d * 260 + t] = v;
            mx = fmaxf(mx, v);
        }
        float ss = 0.f;
        for (int d = 0; d < 32; d++) {
            float e = __expf(ek[d * 260 + t] - mx);
            ek[d * 260 + t] = e; ss += e;
        }
        float qsc = 0.17677669529663687f / ss;     // DIM_HEAD^-0.5 / sum
        float* qg = g_q + (size_t)(bb * HID + h * 32) * NPOS + pos;
        for (int d = 0; d < 32; d++)
            qg[(size_t)d * NPOS] = ek[d * 260 + t] * qsc;

        // ---------- K (exp, no max subtraction; values ~N(0,1)) ----------
        loadW(Wc, wqkv + (size_t)(HID + h * 32) * 64, t);
        for (int d = 0; d < 32; d++)
            ek[d * 260 + t] = __expf(dot64(Wc + d * 64, xp));

        // ---------- V ----------
        loadW(Wc, wqkv + (size_t)(2 * HID + h * 32) * 64, t);
        for (int d = 0; d < 32; d++)
            vv[d * 260 + t] = dot64(Wc + d * 64, xp);
        __syncthreads();

        // ---------- stage B: ctx[d,e] += sum_tt ek[d,tt]*vv[e,tt], Z[d] += sum ek ----------
        u64 acc0 = 0, acc1 = 0, acc2 = 0, acc3 = 0, za = 0;
        const float* ekr = ek + d_own * 260;
#pragma unroll 4
        for (int tt = 0; tt < TPB; tt += 4) {
            ulonglong2 ap  = *(const ulonglong2*)(ekr + tt);
            ulonglong2 bv0 = *(const ulonglong2*)(vv + (e0     ) * 260 + tt);
            ulonglong2 bv1 = *(const ulonglong2*)(vv + (e0 +  8) * 260 + tt);
            ulonglong2 bv2 = *(const ulonglong2*)(vv + (e0 + 16) * 260 + tt);
            ulonglong2 bv3 = *(const ulonglong2*)(vv + (e0 + 24) * 260 + tt);
            acc0 = ffma2(ap.x, bv0.x, acc0); acc0 = ffma2(ap.y, bv0.y, acc0);
            acc1 = ffma2(ap.x, bv1.x, acc1); acc1 = ffma2(ap.y, bv1.y, acc1);
            acc2 = ffma2(ap.x, bv2.x, acc2); acc2 = ffma2(ap.y, bv2.y, acc2);
            acc3 = ffma2(ap.x, bv3.x, acc3); acc3 = ffma2(ap.y, bv3.y, acc3);
            if (e0 == 0) za = fadd2(za, fadd2(ap.x, ap.y));
        }
        float* cb = g_ctx + (size_t)((bb * HEADS + h) * DHEAD + d_own) * DHEAD;
        atomicAdd(cb + e0,      hsum2(acc0));
        atomicAdd(cb + e0 +  8, hsum2(acc1));
        atomicAdd(cb + e0 + 16, hsum2(acc2));
        atomicAdd(cb + e0 + 24, hsum2(acc3));
        if (e0 == 0) atomicAdd(g_Z + (bb * HEADS + h) * DHEAD + d_own, hsum2(za));
        // next head's loadW pre-sync protects tile reuse
    }
}

// ---------------- kernel 2: fold  Mt[i=h*32+d][o] = sum_e W_out[o][h*32+e] * ctx[h,d,e] / Z[h,d]
__global__ void la_fold_kernel(const float* __restrict__ wout) {
    int bb = blockIdx.x;
    for (int idx = threadIdx.x; idx < HID * CC; idx += blockDim.x) {
        int i  = idx >> 6;        // hid index (h*32+d)
        int o  = idx & 63;        // output channel
        int h  = i >> 5;
        int d  = i & 31;
        const float* cp = g_ctx + (size_t)((bb * HEADS + h) * DHEAD + d) * DHEAD;
        const float* wp = wout + (size_t)o * HID + h * DHEAD;
        float acc = 0.f;
#pragma unroll
        for (int e = 0; e < 32; e++) acc += wp[e] * cp[e];
        g_M[(size_t)bb * HID * CC + idx] = acc / g_Z[(bb * HEADS + h) * DHEAD + d];
    }
}

// ---------------- kernel 3: y = LN2( Mt^T @ q + b_out ) ----------------
// 4-thread group: 4 positions shared, 16 channels per thread.
// smem: Mt[8192] bo[64] g2s[64] b2s[64] = 8384 floats = 33536 B
#define SM2_FLOATS (8192 + 64 + 64 + 64)

__global__ __launch_bounds__(TPB, 2)
void la_pass2_kernel(const float* __restrict__ bout, const float* __restrict__ g2,
                     const float* __restrict__ b2, float* __restrict__ out) {
    extern __shared__ float sm2[];
    float* Mt  = sm2;             // 8192  (layout [i][o], o contiguous)
    float* bo  = Mt + 8192;       // 64
    float* g2s = bo + 64;         // 64
    float* b2s = g2s + 64;        // 64

    const int t  = threadIdx.x;
    const int bb = blockIdx.y;
    const int g  = t >> 2;        // group 0..63 -> 4 positions each
    const int c  = t & 3;         // channel quarter: channels [c*16, c*16+16)
    const int pbase = blockIdx.x * TPB + g * 4;

    for (int i = t; i < (HID * CC) / 4; i += TPB)
        ((float4*)Mt)[i] = ((const float4*)(g_M + (size_t)bb * HID * CC))[i];
    if (t < 64) { bo[t] = bout[t]; g2s[t] = g2[t]; b2s[t] = b2[t]; }
    __syncthreads();

    const float* qb = g_q + (size_t)bb * HID * NPOS + pbase;

    // acc[p][k]: packed pair (y[p][c*16+2k], y[p][c*16+2k+1])
    u64 acc[4][8];
#pragma unroll
    for (int p = 0; p < 4; p++)
#pragma unroll
        for (int k = 0; k < 8; k++) acc[p][k] = 0;

    const float* mtc = Mt + c * 16;
#pragma unroll 4
    for (int i = 0; i < HID; i++) {
        float4 q4 = *(const float4*)(qb + (size_t)i * NPOS);   // 4 positions, contiguous
        u64 qd0 = pack2(q4.x, q4.x);
        u64 qd1 = pack2(q4.y, q4.y);
        u64 qd2 = pack2(q4.z, q4.z);
        u64 qd3 = pack2(q4.w, q4.w);
        const ulonglong2* mp = (const ulonglong2*)(mtc + i * 64);
#pragma unroll
        for (int j = 0; j < 4; j++) {
            ulonglong2 m = mp[j];
            acc[0][2 * j]     = ffma2(m.x, qd0, acc[0][2 * j]);
            acc[0][2 * j + 1] = ffma2(m.y, qd0, acc[0][2 * j + 1]);
            acc[1][2 * j]     = ffma2(m.x, qd1, acc[1][2 * j]);
            acc[1][2 * j + 1] = ffma2(m.y, qd1, acc[1][2 * j + 1]);
            acc[2][2 * j]     = ffma2(m.x, qd2, acc[2][2 * j]);
            acc[2][2 * j + 1] = ffma2(m.y, qd2, acc[2][2 * j + 1]);
            acc[3][2 * j]     = ffma2(m.x, qd3, acc[3][2 * j]);
            acc[3][2 * j + 1] = ffma2(m.y, qd3, acc[3][2 * j + 1]);
        }
    }

    // add bias (packed pairs from smem), then partial LN stats over own 16 channels
    float s[4], s2[4];
#pragma unroll
    for (int p = 0; p < 4; p++) { s[p] = 0.f; s2[p] = 0.f; }
    const u64* bop = (const u64*)(bo + c * 16);
#pragma unroll
    for (int k = 0; k < 8; k++) {
        u64 bpair = bop[k];
#pragma unroll
        for (int p = 0; p < 4; p++) {
            acc[p][k] = fadd2(acc[p][k], bpair);
            float lo, hi; unpack2(acc[p][k], lo, hi);
            s[p]  += lo + hi;
            s2[p] += lo * lo + hi * hi;
        }
    }
    // reduce across the 4-thread group (lanes differ in bits 0-1 -> same warp)
#pragma unroll
    for (int p = 0; p < 4; p++) {
        s[p]  += __shfl_xor_sync(0xffffffffu, s[p], 1);
        s2[p] += __shfl_xor_sync(0xffffffffu, s2[p], 1);
        s[p]  += __shfl_xor_sync(0xffffffffu, s[p], 2);
        s2[p] += __shfl_xor_sync(0xffffffffu, s2[p], 2);
    }
    float mean[4], rstd[4];
#pragma unroll
    for (int p = 0; p < 4; p++) {
        mean[p] = s[p] * (1.f / 64.f);
        rstd[p] = rsqrtf(s2[p] * (1.f / 64.f) - mean[p] * mean[p] + 1e-5f);
    }

    // store: per channel, 4 consecutive positions -> STG.128
    float* ob = out + (size_t)bb * CC * NPOS + pbase;
#pragma unroll
    for (int k = 0; k < 8; k++) {
        int o0 = c * 16 + 2 * k;
        float ga = g2s[o0],     ba = b2s[o0];
        float gb = g2s[o0 + 1], bbv = b2s[o0 + 1];
        float lo0, hi0, lo1, hi1, lo2, hi2, lo3, hi3;
        unpack2(acc[0][k], lo0, hi0);
        unpack2(acc[1][k], lo1, hi1);
        unpack2(acc[2][k], lo2, hi2);
        unpack2(acc[3][k], lo3, hi3);
        float4 va, vb;
        va.x = (lo0 - mean[0]) * rstd[0] * ga + ba;
        va.y = (lo1 - mean[1]) * rstd[1] * ga + ba;
        va.z = (lo2 - mean[2]) * rstd[2] * ga + ba;
        va.w = (lo3 - mean[3]) * rstd[3] * ga + ba;
        vb.x = (hi0 - mean[0]) * rstd[0] * gb + bbv;
        vb.y = (hi1 - mean[1]) * rstd[1] * gb + bbv;
        vb.z = (hi2 - mean[2]) * rstd[2] * gb + bbv;
        vb.w = (hi3 - mean[3]) * rstd[3] * gb + bbv;
        *(float4*)(ob + (size_t)o0 * NPOS)       = va;
        *(float4*)(ob + (size_t)(o0 + 1) * NPOS) = vb;
    }
}

// ---------------- launch ----------------
extern "C" void kernel_launch(void* const* d_in, const int* in_sizes, int n_in,
                              void* d_out, int out_size) {
    (void)in_sizes; (void)n_in; (void)out_size;
    const float* x    = (const float*)d_in[0];
    const float* g1   = (const float*)d_in[1];
    const float* b1   = (const float*)d_in[2];
    const float* wqkv = (const float*)d_in[3];
    const float* wout = (const float*)d_in[4];
    const float* bout = (const float*)d_in[5];
    const float* g2   = (const float*)d_in[6];
    const float* b2   = (const float*)d_in[7];
    float* y = (float*)d_out;

    cudaFuncSetAttribute(la_pass1_kernel, cudaFuncAttributeMaxDynamicSharedMemorySize,
                         SM1_FLOATS * (int)sizeof(float));
    cudaFuncSetAttribute(la_pass2_kernel, cudaFuncAttributeMaxDynamicSharedMemorySize,
                         SM2_FLOATS * (int)sizeof(float));

    la_zero_kernel<<<33, 256>>>();
    la_pass1_kernel<<<dim3(NPOS / TPB, BB), TPB, SM1_FLOATS * sizeof(float)>>>(x, g1, b1, wqkv);
    la_fold_kernel<<<BB, 256>>>(wout);
    la_pass2_kernel<<<dim3(NPOS / TPB, BB), TPB, SM2_FLOATS * sizeof(float)>>>(bout, g2, b2, y);
}

// round 8
// speedup vs baseline: 1.7612x; 1.0992x over previous
#include <cuda_runtime.h>
#include <cstdint>

#define BB    2
#define CC    64
#define NPOS  131072
#define HEADS 4
#define DHEAD 32
#define HID   128
#define TPB   256
#define POSB  256

typedef unsigned long long u64;

// ---------------- device scratch (static, allowed) ----------------
__device__ float g_q[(size_t)BB * HID * NPOS];         // softmaxed+scaled q, [b][h*32+d][n]
__device__ float g_ctx[BB * HEADS * DHEAD * DHEAD];    // raw sum exp(k_d)*v_e
__device__ float g_Z[BB * HEADS * DHEAD];              // sum exp(k_d)
__device__ float g_M[BB * HID * CC];                   // folded, permuted: Mt2[b][i][j][c][r]

// ---------------- f32x2 helpers ----------------
__device__ __forceinline__ u64 pack2(float lo, float hi) {
    u64 r; asm("mov.b64 %0, {%1,%2};" : "=l"(r) : "f"(lo), "f"(hi)); return r;
}
__device__ __forceinline__ u64 ffma2(u64 a, u64 b, u64 c) {
    u64 d; asm("fma.rn.f32x2 %0, %1, %2, %3;" : "=l"(d) : "l"(a), "l"(b), "l"(c)); return d;
}
__device__ __forceinline__ u64 fadd2(u64 a, u64 b) {
    u64 d; asm("add.rn.f32x2 %0, %1, %2;" : "=l"(d) : "l"(a), "l"(b)); return d;
}
__device__ __forceinline__ float hsum2(u64 a) {
    float lo, hi; asm("mov.b64 {%0,%1}, %2;" : "=f"(lo), "=f"(hi) : "l"(a)); return lo + hi;
}
__device__ __forceinline__ void unpack2(u64 a, float& lo, float& hi) {
    asm("mov.b64 {%0,%1}, %2;" : "=f"(lo), "=f"(hi) : "l"(a));
}

// ---------------- kernel 0: zero accumulators ----------------
__global__ void la_zero_kernel() {
    int i = blockIdx.x * blockDim.x + threadIdx.x;
    if (i < BB * HEADS * DHEAD * DHEAD) g_ctx[i] = 0.f;
    if (i < BB * HEADS * DHEAD)         g_Z[i]   = 0.f;
}

// ================= pass1: LN1 + tiled QKV GEMM + q softmax + ctx/Z =================
// smem float layout:
//   xs [64][260]        16640   xn transposed (k-major, positions contiguous)
//   ek [32][260]         8320   staging: Q logits / exp(K)
//   vv [32][260]         8320   V tile
//   Wct2 2 bufs 64x18 u64 4608  W chunk, row-pairs packed as f32x2, +2 u64 pad/row
//   g1s/b1s               128
#define XS_SZ   (64 * 260)
#define EK_SZ   (32 * 260)
#define W_OFF   (XS_SZ + EK_SZ + EK_SZ)           // 33280 floats (16B aligned)
#define W_BUF_U64 (64 * 18)
#define GB_OFF  (W_OFF + 2 * W_BUF_U64 * 2)       // 37888
#define SM1_FLOATS (GB_OFF + 128)                 // 38016 floats = 152064 B

// cooperative W chunk load: rows [0,32) of wsrc (row-major [r][64]) packed as
// wbuf[k*18 + r2] = (w[2*r2][k], w[2*r2+1][k])
__device__ __forceinline__ void loadW2(u64* wbuf, const float* __restrict__ wsrc, int t) {
#pragma unroll
    for (int i = 0; i < 4; i++) {
        int p  = t + i * 256;      // 0..1023
        int r2 = p & 15;           // row-pair 0..15
        int k  = p >> 4;           // 0..63
        float w0 = __ldg(wsrc + (2 * r2)     * 64 + k);
        float w1 = __ldg(wsrc + (2 * r2 + 1) * 64 + k);
        wbuf[k * 18 + r2] = pack2(w0, w1);
    }
}

// 32-row x 256-pos x 64-k GEMM tile: thread (rg,pg) -> rows rg*8+{0..7} (as 4 pairs),
// positions pg*4+{0..3}
__device__ __forceinline__ void gemm_chunk(const u64* __restrict__ wbuf,
                                           const float* __restrict__ xs,
                                           int rg, int pg, u64 (&acc)[4][4]) {
#pragma unroll
    for (int rp = 0; rp < 4; rp++)
#pragma unroll
        for (int p = 0; p < 4; p++) acc[rp][p] = 0;
#pragma unroll 4
    for (int k = 0; k < 64; k++) {
        const u64* wk = wbuf + k * 18 + rg * 4;
        ulonglong2 wa = *(const ulonglong2*)wk;         // row pairs rp=0,1 (broadcast)
        ulonglong2 wb = *(const ulonglong2*)(wk + 2);   // row pairs rp=2,3
        float4 xv = *(const float4*)(xs + k * 260 + pg * 4);  // 4 positions, conflict-free
        u64 x0 = pack2(xv.x, xv.x);
        u64 x1 = pack2(xv.y, xv.y);
        u64 x2 = pack2(xv.z, xv.z);
        u64 x3 = pack2(xv.w, xv.w);
        acc[0][0] = ffma2(wa.x, x0, acc[0][0]);
        acc[0][1] = ffma2(wa.x, x1, acc[0][1]);
        acc[0][2] = ffma2(wa.x, x2, acc[0][2]);
        acc[0][3] = ffma2(wa.x, x3, acc[0][3]);
        acc[1][0] = ffma2(wa.y, x0, acc[1][0]);
        acc[1][1] = ffma2(wa.y, x1, acc[1][1]);
        acc[1][2] = ffma2(wa.y, x2, acc[1][2]);
        acc[1][3] = ffma2(wa.y, x3, acc[1][3]);
        acc[2][0] = ffma2(wb.x, x0, acc[2][0]);
        acc[2][1] = ffma2(wb.x, x1, acc[2][1]);
        acc[2][2] = ffma2(wb.x, x2, acc[2][2]);
        acc[2][3] = ffma2(wb.x, x3, acc[2][3]);
        acc[3][0] = ffma2(wb.y, x0, acc[3][0]);
        acc[3][1] = ffma2(wb.y, x1, acc[3][1]);
        acc[3][2] = ffma2(wb.y, x2, acc[3][2]);
        acc[3][3] = ffma2(wb.y, x3, acc[3][3]);
    }
}

__device__ __forceinline__ void store_tile(float* __restrict__ dst, const u64 (&acc)[4][4],
                                           int rg, int pg, bool do_exp) {
#pragma unroll
    for (int rp = 0; rp < 4; rp++) {
        int row = rg * 8 + 2 * rp;
#pragma unroll
        for (int p = 0; p < 4; p++) {
            float lo, hi; unpack2(acc[rp][p], lo, hi);
            if (do_exp) { lo = __expf(lo); hi = __expf(hi); }
            dst[row * 260 + pg * 4 + p]       = lo;
            dst[(row + 1) * 260 + pg * 4 + p] = hi;
        }
    }
}

__global__ __launch_bounds__(TPB)
void la_pass1_kernel(const float* __restrict__ x, const float* __restrict__ g1,
                     const float* __restrict__ b1, const float* __restrict__ wqkv) {
    extern __shared__ float sm1[];
    float* xs  = sm1;
    float* ek  = sm1 + XS_SZ;
    float* vv  = ek + EK_SZ;
    u64*   wb0 = (u64*)(sm1 + W_OFF);
    u64*   wb1 = wb0 + W_BUF_U64;
    float* g1s = sm1 + GB_OFF;
    float* b1s = g1s + 64;

    const int t   = threadIdx.x;
    const int bb  = blockIdx.y;
    const int pos = blockIdx.x * POSB + t;
    const int rg  = t >> 6;        // 0..3 (row group: 8 rows)
    const int pg  = t & 63;        // 0..63 (pos group: 4 positions)

    if (t < 64) { g1s[t] = g1[t]; b1s[t] = b1[t]; }

    // ---- phase 0: load x column, LN stats, normalize, write xs transposed ----
    {
        const float* xb = x + (size_t)bb * CC * NPOS + pos;
        u64 xp[32];
        u64 sa = 0, s2a = 0;
#pragma unroll
        for (int i = 0; i < 32; i++) {
            float a  = __ldg(xb + (size_t)(2 * i)     * NPOS);
            float bv = __ldg(xb + (size_t)(2 * i + 1) * NPOS);
            u64 p = pack2(a, bv);
            xp[i] = p;
            sa  = fadd2(sa, p);
            s2a = ffma2(p, p, s2a);
        }
        float s  = hsum2(sa);
        float s2 = hsum2(s2a);
        float mean = s * (1.f / 64.f);
        float rstd = rsqrtf(s2 * (1.f / 64.f) - mean * mean + 1e-5f);
        __syncthreads();                      // g1s/b1s ready
#pragma unroll
        for (int i = 0; i < 32; i++) {
            float k1a = rstd * g1s[2 * i];
            float k1b = rstd * g1s[2 * i + 1];
            float k2a = b1s[2 * i]     - mean * k1a;
            float k2b = b1s[2 * i + 1] - mean * k1b;
            u64 xn = ffma2(xp[i], pack2(k1a, k1b), pack2(k2a, k2b));
            float lo, hi; unpack2(xn, lo, hi);
            xs[(2 * i)     * 260 + t] = lo;    // lanes consecutive -> conflict-free
            xs[(2 * i + 1) * 260 + t] = hi;
        }
    }
    loadW2(wb0, wqkv, t);                     // Q rows, head 0
    __syncthreads();                          // xs + wb0 ready

    const int d_own = t >> 3;       // stage B ownership
    const int e0    = t & 7;

    u64 acc[4][4];

    for (int h = 0; h < HEADS; h++) {
        // interval 1: Q GEMM -> ek (raw); prefetch K chunk
        gemm_chunk(wb0, xs, rg, pg, acc);
        store_tile(ek, acc, rg, pg, false);
        loadW2(wb1, wqkv + (size_t)(HID + h * 32) * 64, t);
        __syncthreads();

        // interval 2: per-position q softmax from ek columns; prefetch V chunk
        {
            float qv[32];
            float mx = -1e30f;
#pragma unroll
            for (int d = 0; d < 32; d++) {
                qv[d] = ek[d * 260 + t];       // lanes consecutive -> conflict-free
                mx = fmaxf(mx, qv[d]);
            }
            float ss = 0.f;
#pragma unroll
            for (int d = 0; d < 32; d++) { qv[d] = __expf(qv[d] - mx); ss += qv[d]; }
            float qsc = 0.17677669529663687f / ss;   // DIM_HEAD^-0.5 / sum
            float* qg = g_q + (size_t)(bb * HID + h * 32) * NPOS + pos;
#pragma unroll
            for (int d = 0; d < 32; d++)
                qg[(size_t)d * NPOS] = qv[d] * qsc;
        }
        loadW2(wb0, wqkv + (size_t)(2 * HID + h * 32) * 64, t);
        __syncthreads();

        // interval 3: K GEMM (exp) -> ek ; V GEMM -> vv
        gemm_chunk(wb1, xs, rg, pg, acc);
        store_tile(ek, acc, rg, pg, true);
        gemm_chunk(wb0, xs, rg, pg, acc);
        store_tile(vv, acc, rg, pg, false);
        __syncthreads();

        // interval 4: stage B (ctx/Z partial sums); prefetch next head's Q chunk
        {
            u64 a0 = 0, a1 = 0, a2 = 0, a3 = 0, za = 0;
            const float* ekr = ek + d_own * 260;
#pragma unroll 4
            for (int tt = 0; tt < POSB; tt += 4) {
                ulonglong2 ap  = *(const ulonglong2*)(ekr + tt);
                ulonglong2 bv0 = *(const ulonglong2*)(vv + (e0     ) * 260 + tt);
                ulonglong2 bv1 = *(const ulonglong2*)(vv + (e0 +  8) * 260 + tt);
                ulonglong2 bv2 = *(const ulonglong2*)(vv + (e0 + 16) * 260 + tt);
                ulonglong2 bv3 = *(const ulonglong2*)(vv + (e0 + 24) * 260 + tt);
                a0 = ffma2(ap.x, bv0.x, a0); a0 = ffma2(ap.y, bv0.y, a0);
                a1 = ffma2(ap.x, bv1.x, a1); a1 = ffma2(ap.y, bv1.y, a1);
                a2 = ffma2(ap.x, bv2.x, a2); a2 = ffma2(ap.y, bv2.y, a2);
                a3 = ffma2(ap.x, bv3.x, a3); a3 = ffma2(ap.y, bv3.y, a3);
                if (e0 == 0) za = fadd2(za, fadd2(ap.x, ap.y));
            }
            float* cb = g_ctx + (size_t)((bb * HEADS + h) * DHEAD + d_own) * DHEAD;
            atomicAdd(cb + e0,      hsum2(a0));
            atomicAdd(cb + e0 +  8, hsum2(a1));
            atomicAdd(cb + e0 + 16, hsum2(a2));
            atomicAdd(cb + e0 + 24, hsum2(a3));
            if (e0 == 0) atomicAdd(g_Z + (bb * HEADS + h) * DHEAD + d_own, hsum2(za));
        }
        if (h < 3) loadW2(wb0, wqkv + (size_t)((h + 1) * 32) * 64, t);
        __syncthreads();
    }
}

// ---------------- kernel 2: fold, permuted layout ----------------
// Mt2 float offset = i*64 + j*16 + c*4 + r  holds  M[i][o = c*16 + 4j + r]
__global__ void la_fold_kernel(const float* __restrict__ wout) {
    int bb = blockIdx.x;
    for (int idx = threadIdx.x; idx < HID * CC; idx += blockDim.x) {
        int i  = idx >> 6;        // hid index (h*32+d)
        int o  = idx & 63;        // output channel
        int h  = i >> 5;
        int d  = i & 31;
        const float* cp = g_ctx + (size_t)((bb * HEADS + h) * DHEAD + d) * DHEAD;
        const float* wp = wout + (size_t)o * HID + h * DHEAD;
        float acc = 0.f;
#pragma unroll
        for (int e = 0; e < 32; e++) acc += wp[e] * cp[e];
        int sidx = i * 64 + ((o >> 2) & 3) * 16 + (o >> 4) * 4 + (o & 3);
        g_M[(size_t)bb * HID * CC + sidx] = acc / g_Z[(bb * HEADS + h) * DHEAD + d];
    }
}

// ---------------- kernel 3: y = LN2( Mt^T @ q + b_out ) ----------------
// 4-thread group: 4 positions shared, 16 channels per thread; conflict-free Mt2 loads.
#define SM2_FLOATS (8192 + 64 + 64 + 64)

__global__ __launch_bounds__(TPB, 2)
void la_pass2_kernel(const float* __restrict__ bout, const float* __restrict__ g2,
                     const float* __restrict__ b2, float* __restrict__ out) {
    extern __shared__ float sm2[];
    float* Mt  = sm2;             // 8192, permuted layout
    float* bo  = Mt + 8192;
    float* g2s = bo + 64;
    float* b2s = g2s + 64;

    const int t  = threadIdx.x;
    const int bb = blockIdx.y;
    const int g  = t >> 2;        // group -> 4 positions
    const int c  = t & 3;         // channel quarter
    const int pbase = blockIdx.x * TPB + g * 4;

    for (int i = t; i < (HID * CC) / 4; i += TPB)
        ((float4*)Mt)[i] = ((const float4*)(g_M + (size_t)bb * HID * CC))[i];
    if (t < 64) { bo[t] = bout[t]; g2s[t] = g2[t]; b2s[t] = b2[t]; }
    __syncthreads();

    const float* qb = g_q + (size_t)bb * HID * NPOS + pbase;

    u64 acc[4][8];
#pragma unroll
    for (int p = 0; p < 4; p++)
#pragma unroll
        for (int k = 0; k < 8; k++) acc[p][k] = 0;

    const float* mtc = Mt + c * 4;
#pragma unroll 4
    for (int i = 0; i < HID; i++) {
        float4 q4 = *(const float4*)(qb + (size_t)i * NPOS);
        u64 qd0 = pack2(q4.x, q4.x);
        u64 qd1 = pack2(q4.y, q4.y);
        u64 qd2 = pack2(q4.z, q4.z);
        u64 qd3 = pack2(q4.w, q4.w);
#pragma unroll
        for (int j = 0; j < 4; j++) {
            // bytes: i*256 + j*64 + c*16 -> 4 c-lanes at 16B stride: conflict-free, 1 wf
            ulonglong2 m = *(const ulonglong2*)(mtc + i * 64 + j * 16);
            acc[0][2 * j]     = ffma2(m.x, qd0, acc[0][2 * j]);
            acc[0][2 * j + 1] = ffma2(m.y, qd0, acc[0][2 * j + 1]);
            acc[1][2 * j]     = ffma2(m.x, qd1, acc[1][2 * j]);
            acc[1][2 * j + 1] = ffma2(m.y, qd1, acc[1][2 * j + 1]);
            acc[2][2 * j]     = ffma2(m.x, qd2, acc[2][2 * j]);
            acc[2][2 * j + 1] = ffma2(m.y, qd2, acc[2][2 * j + 1]);
            acc[3][2 * j]     = ffma2(m.x, qd3, acc[3][2 * j]);
            acc[3][2 * j + 1] = ffma2(m.y, qd3, acc[3][2 * j + 1]);
        }
    }

    // bias + partial LN stats over own 16 channels
    float s[4], s2[4];
#pragma unroll
    for (int p = 0; p < 4; p++) { s[p] = 0.f; s2[p] = 0.f; }
    const u64* bop = (const u64*)(bo + c * 16);
#pragma unroll
    for (int k = 0; k < 8; k++) {
        u64 bpair = bop[k];
#pragma unroll
        for (int p = 0; p < 4; p++) {
            acc[p][k] = fadd2(acc[p][k], bpair);
            float lo, hi; unpack2(acc[p][k], lo, hi);
            s[p]  += lo + hi;
            s2[p] += lo * lo + hi * hi;
        }
    }
#pragma unroll
    for (int p = 0; p < 4; p++) {
        s[p]  += __shfl_xor_sync(0xffffffffu, s[p], 1);
        s2[p] += __shfl_xor_sync(0xffffffffu, s2[p], 1);
        s[p]  += __shfl_xor_sync(0xffffffffu, s[p], 2);
        s2[p] += __shfl_xor_sync(0xffffffffu, s2[p], 2);
    }
    float mean[4], rstd[4];
#pragma unroll
    for (int p = 0; p < 4; p++) {
        mean[p] = s[p] * (1.f / 64.f);
        rstd[p] = rsqrtf(s2[p] * (1.f / 64.f) - mean[p] * mean[p] + 1e-5f);
    }

    float* ob = out + (size_t)bb * CC * NPOS + pbase;
#pragma unroll
    for (int k = 0; k < 8; k++) {
        int o0 = c * 16 + 2 * k;
        float ga = g2s[o0],     ba  = b2s[o0];
        float gb = g2s[o0 + 1], bbv = b2s[o0 + 1];
        float lo0, hi0, lo1, hi1, lo2, hi2, lo3, hi3;
        unpack2(acc[0][k], lo0, hi0);
        unpack2(acc[1][k], lo1, hi1);
        unpack2(acc[2][k], lo2, hi2);
        unpack2(acc[3][k], lo3, hi3);
        float4 va, vb;
        va.x = (lo0 - mean[0]) * rstd[0] * ga + ba;
        va.y = (lo1 - mean[1]) * rstd[1] * ga + ba;
        va.z = (lo2 - mean[2]) * rstd[2] * ga + ba;
        va.w = (lo3 - mean[3]) * rstd[3] * ga + ba;
        vb.x = (hi0 - mean[0]) * rstd[0] * gb + bbv;
        vb.y = (hi1 - mean[1]) * rstd[1] * gb + bbv;
        vb.z = (hi2 - mean[2]) * rstd[2] * gb + bbv;
        vb.w = (hi3 - mean[3]) * rstd[3] * gb + bbv;
        *(float4*)(ob + (size_t)o0 * NPOS)       = va;
        *(float4*)(ob + (size_t)(o0 + 1) * NPOS) = vb;
    }
}

// ---------------- launch ----------------
extern "C" void kernel_launch(void* const* d_in, const int* in_sizes, int n_in,
                              void* d_out, int out_size) {
    (void)in_sizes; (void)n_in; (void)out_size;
    const float* x    = (const float*)d_in[0];
    const float* g1   = (const float*)d_in[1];
    const float* b1   = (const float*)d_in[2];
    const float* wqkv = (const float*)d_in[3];
    const float* wout = (const float*)d_in[4];
    const float* bout = (const float*)d_in[5];
    const float* g2   = (const float*)d_in[6];
    const float* b2   = (const float*)d_in[7];
    float* y = (float*)d_out;

    cudaFuncSetAttribute(la_pass1_kernel, cudaFuncAttributeMaxDynamicSharedMemorySize,
                         SM1_FLOATS * (int)sizeof(float));
    cudaFuncSetAttribute(la_pass2_kernel, cudaFuncAttributeMaxDynamicSharedMemorySize,
                         SM2_FLOATS * (int)sizeof(float));

    la_zero_kernel<<<33, 256>>>();
    la_pass1_kernel<<<dim3(NPOS / POSB, BB), TPB, SM1_FLOATS * sizeof(float)>>>(x, g1, b1, wqkv);
    la_fold_kernel<<<BB, 256>>>(wout);
    la_pass2_kernel<<<dim3(NPOS / TPB, BB), TPB, SM2_FLOATS * sizeof(float)>>>(bout, g2, b2, y);
}